// round 6
// baseline (speedup 1.0000x reference)
#include <cuda_runtime.h>
#include <math.h>

#define HH       256
#define NHEADS   8
#define MAX_N    1024
#define MAX_EDGES 600000
#define ETILE    256
#define SUB      32

// ---------------- scratch (device globals; no allocation allowed) -------------
__device__ int    g_cnt2[MAX_N * SUB];
__device__ int    g_cur2[MAX_N * SUB];
__device__ int    g_roff[MAX_N + 1];
__device__ int    g_deg1[MAX_N];
__device__ int    g_deg2[MAX_N];
__device__ float  g_asum[MAX_N * 3];
__device__ float4 g_epack[MAX_EDGES];          // (src_as_float, a0, a1, a2)
__device__ float  g_h [MAX_N * HH];
__device__ float  g_xl[MAX_N * HH];
__device__ float  g_xr[MAX_N * HH];
__device__ float  g_A [MAX_N * HH];
__device__ float  g_B [MAX_N * HH];
__device__ float  g_dummy[1024];               // probe output (never read)

// ---------------- f32x2 packed helpers (bit-exact fp32, 2x FFMA tput) ---------
__device__ __forceinline__ unsigned long long pk2(float a, float b) {
    unsigned long long r;
    asm("mov.b64 %0, {%1,%2};" : "=l"(r) : "f"(a), "f"(b));
    return r;
}
__device__ __forceinline__ void upk2(unsigned long long v, float& a, float& b) {
    asm("mov.b64 {%0,%1}, %2;" : "=f"(a), "=f"(b) : "l"(v));
}
__device__ __forceinline__ void fma2(unsigned long long& d, unsigned long long a,
                                     unsigned long long b) {
    asm("fma.rn.f32x2 %0, %1, %2, %0;" : "+l"(d) : "l"(a), "l"(b));
}

// ---------------- setup kernels ------------------------------------------------
// embedding + per-node scratch init fused (block n handles node n)
__global__ void k_embinit(const float* __restrict__ x, const float* __restrict__ W,
                          const float* __restrict__ b) {
    int n = blockIdx.x, t = threadIdx.x;
    g_h[n * HH + t] = x[n] * W[t] + b[t];
    if (t < SUB) g_cnt2[n * SUB + t] = 0;
    if (t == 32) { g_deg1[n] = 0; g_deg2[n] = 0; }
    if (t == 33) {
        g_asum[3 * n] = 0.f; g_asum[3 * n + 1] = 0.f; g_asum[3 * n + 2] = 0.f;
    }
}

__global__ void k_edge_stats(const int* __restrict__ ei, const float* __restrict__ ea,
                             int E) {
    int e = blockIdx.x * blockDim.x + threadIdx.x;
    if (e >= E) return;
    int s = ei[e], d = ei[E + e];
    float a0 = ea[3 * e], a1 = ea[3 * e + 1], a2 = ea[3 * e + 2];
    atomicAdd(&g_cnt2[d * SUB + (e & (SUB - 1))], 1);     // RED, no return
    atomicAdd(&g_asum[3 * d + 0], a0);
    atomicAdd(&g_asum[3 * d + 1], a1);
    atomicAdd(&g_asum[3 * d + 2], a2);
    // argmax with first-occurrence ties (matches jnp.argmax)
    int best = 0; float bv = a0;
    if (a1 > bv) { best = 1; bv = a1; }
    if (a2 > bv) { best = 2; }
    if (best == 1) { atomicAdd(&g_deg1[s], 1); atomicAdd(&g_deg1[d], 1); }
    else if (best == 2) { atomicAdd(&g_deg2[s], 1); atomicAdd(&g_deg2[d], 1); }
}

// prefix scan of segment lengths (cnt+1 for self-loop), sub-bucket bases,
// and self-loop packed entry
__global__ void k_scan(int N) {
    __shared__ int sc[1024];
    int t = threadIdx.x;
    int subc[SUB];
    int cnt = 0;
    if (t < N) {
#pragma unroll
        for (int s = 0; s < SUB; s++) { subc[s] = g_cnt2[t * SUB + s]; cnt += subc[s]; }
    }
    int len = (t < N) ? (cnt + 1) : 0;
    sc[t] = len;
    __syncthreads();
    for (int off = 1; off < 1024; off <<= 1) {
        int v = (t >= off) ? sc[t - off] : 0;
        __syncthreads();
        sc[t] += v;
        __syncthreads();
    }
    if (t < N) {
        int incl = sc[t];
        int excl = incl - len;
        g_roff[t + 1] = incl;
        if (t == 0) g_roff[0] = 0;
        int off = excl;
#pragma unroll
        for (int s = 0; s < SUB; s++) { g_cur2[t * SUB + s] = off; off += subc[s]; }
        int slot = excl + cnt;                     // self-loop at end of segment
        float c = fmaxf((float)cnt, 1.0f);
        g_epack[slot] = make_float4(__int_as_float(t),
                                    g_asum[3 * t + 0] / c,
                                    g_asum[3 * t + 1] / c,
                                    g_asum[3 * t + 2] / c);
    }
}

__global__ void k_scatter(const int* __restrict__ ei, const float* __restrict__ ea,
                          int E) {
    int e = blockIdx.x * blockDim.x + threadIdx.x;
    if (e >= E) return;
    int s = ei[e], d = ei[E + e];
    int pos = atomicAdd(&g_cur2[d * SUB + (e & (SUB - 1))], 1);
    g_epack[pos] = make_float4(__int_as_float(s), ea[3 * e], ea[3 * e + 1], ea[3 * e + 2]);
}

// xl = h@Wl + bl ; xr = h@Wr + br
// block = 4 nodes x 128 channels, weights double-buffered through smem
#define NLN 4
#define NLC 16
__global__ void __launch_bounds__(128)
k_nodelin(const float* __restrict__ Wl, const float* __restrict__ bl,
          const float* __restrict__ Wr, const float* __restrict__ br,
          int l, int N) {
    __shared__ float hr[NLN][HH];
    __shared__ float wbuf[2][2][NLC][128];
    int nb = blockIdx.x * NLN;
    int chb = blockIdx.y * 128;
    int t = threadIdx.x;
    int ch = chb + t;
    for (int idx = t; idx < NLN * HH; idx += 128) {
        int r = idx >> 8, c = idx & 255;
        int n = nb + r;
        hr[r][c] = (n < N) ? g_h[n * HH + c] : 0.f;
    }
    const float* WL = Wl + (size_t)l * HH * HH + chb;
    const float* WR = Wr + (size_t)l * HH * HH + chb;
#pragma unroll
    for (int r = 0; r < NLC; r++) {
        wbuf[0][0][r][t] = WL[r * HH + t];
        wbuf[0][1][r][t] = WR[r * HH + t];
    }
    float aL[NLN], aR[NLN];
    float blv = bl[l * HH + ch], brv = br[l * HH + ch];
#pragma unroll
    for (int r = 0; r < NLN; r++) { aL[r] = blv; aR[r] = brv; }
    const int nch = HH / NLC;
    for (int k = 0; k < nch; k++) {
        int buf = k & 1;
        __syncthreads();
        if (k + 1 < nch) {
            int c0 = (k + 1) * NLC;
#pragma unroll
            for (int r = 0; r < NLC; r++) {
                wbuf[buf ^ 1][0][r][t] = WL[(c0 + r) * HH + t];
                wbuf[buf ^ 1][1][r][t] = WR[(c0 + r) * HH + t];
            }
        }
#pragma unroll
        for (int r = 0; r < NLC; r++) {
            int c = k * NLC + r;
            float wl = wbuf[buf][0][r][t];
            float wr = wbuf[buf][1][r][t];
#pragma unroll
            for (int n = 0; n < NLN; n++) {
                aL[n] = fmaf(hr[n][c], wl, aL[n]);
                aR[n] = fmaf(hr[n][c], wr, aR[n]);
            }
        }
    }
#pragma unroll
    for (int r = 0; r < NLN; r++) {
        int n = nb + r;
        if (n < N) { g_xl[n * HH + ch] = aL[r]; g_xr[n * HH + ch] = aR[r]; }
    }
}

// one block (128 threads, float2/thread) per destination node: fused GATv2
// scoring + softmax + aggregation + residual + LayerNorm + ReLU.
// No running max (scores O(0.05) -> exp() safe): every 4-edge group is fully
// independent, no serial rescale chain.
__global__ void __launch_bounds__(128)
k_gat(const float* __restrict__ We, const float* __restrict__ att,
      const float* __restrict__ gb, const float* __restrict__ lng,
      const float* __restrict__ lnb, int l) {
    __shared__ float4 ep[ETILE];
    __shared__ float red[4];
    int n = blockIdx.x, t = threadIdx.x;
    int wid = t >> 5, lane = t & 31;
    int ch0 = 2 * t;
    int head = t >> 4;
    int hc = ch0 & 31;
    float2 xr2 = *(const float2*)&g_xr[n * HH + ch0];
    float2 hres = *(const float2*)&g_h[n * HH + ch0];
    float att0 = att[(l * NHEADS + head) * 32 + hc];
    float att1 = att[(l * NHEADS + head) * 32 + hc + 1];
    float we00 = We[(l * 3 + 0) * HH + ch0], we01 = We[(l * 3 + 0) * HH + ch0 + 1];
    float we10 = We[(l * 3 + 1) * HH + ch0], we11 = We[(l * 3 + 1) * HH + ch0 + 1];
    float we20 = We[(l * 3 + 2) * HH + ch0], we21 = We[(l * 3 + 2) * HH + ch0 + 1];
    int e0 = g_roff[n], e1 = g_roff[n + 1];

    float den = 0.f, acc0 = 0.f, acc1 = 0.f;
    for (int t0 = e0; t0 < e1; t0 += ETILE) {
        int cnt = min(ETILE, e1 - t0);
        __syncthreads();
        for (int k = t; k < cnt; k += 128) ep[k] = g_epack[t0 + k];
        __syncthreads();
#pragma unroll 2
        for (int g = 0; g < cnt; g += 4) {
            float2 xv[4];
            float al[4];
#pragma unroll
            for (int u = 0; u < 4; u++) {
                int idx = min(g + u, cnt - 1);
                float4 e = ep[idx];
                int s = __float_as_int(e.x);
                xv[u] = *(const float2*)&g_xl[s * HH + ch0];
                float s0 = xv[u].x + xr2.x + e.y * we00 + e.z * we10 + e.w * we20;
                float s1 = xv[u].y + xr2.y + e.y * we01 + e.z * we11 + e.w * we21;
                s0 = s0 > 0.f ? s0 : 0.2f * s0;
                s1 = s1 > 0.f ? s1 : 0.2f * s1;
                float v = s0 * att0 + s1 * att1;
                al[u] = (g + u < cnt) ? v : -1e30f;
            }
            // multi-reduce: 4 head-sums over 16-lane groups in 5 shfls
            float p0 = (lane & 8) ? al[2] : al[0];
            float q0 = (lane & 8) ? al[0] : al[2];
            float p1 = (lane & 8) ? al[3] : al[1];
            float q1 = (lane & 8) ? al[1] : al[3];
            p0 += __shfl_xor_sync(0xffffffffu, q0, 8);
            p1 += __shfl_xor_sync(0xffffffffu, q1, 8);
            float pa = (lane & 4) ? p1 : p0;
            float qa = (lane & 4) ? p0 : p1;
            pa += __shfl_xor_sync(0xffffffffu, qa, 4);
            pa += __shfl_xor_sync(0xffffffffu, pa, 2);
            pa += __shfl_xor_sync(0xffffffffu, pa, 1);
            int base = lane & 16;
#pragma unroll
            for (int u = 0; u < 4; u++) {
                float w = __expf(__shfl_sync(0xffffffffu, pa, base + (u << 2)));
                den += w;
                acc0 = fmaf(w, xv[u].x, acc0);
                acc1 = fmaf(w, xv[u].y, acc1);
            }
        }
    }
    float inv = 1.0f / den;
    float o0 = acc0 * inv + gb[l * HH + ch0]     + hres.x;
    float o1 = acc1 * inv + gb[l * HH + ch0 + 1] + hres.y;

    // LayerNorm over 256 channels (block reduce over 4 warps), then ReLU
    float v = o0 + o1;
#pragma unroll
    for (int o = 16; o > 0; o >>= 1) v += __shfl_xor_sync(0xffffffffu, v, o);
    if (lane == 0) red[wid] = v;
    __syncthreads();
    float mu = (red[0] + red[1] + red[2] + red[3]) * (1.0f / HH);
    float d0 = o0 - mu, d1 = o1 - mu;
    float q = d0 * d0 + d1 * d1;
#pragma unroll
    for (int o = 16; o > 0; o >>= 1) q += __shfl_xor_sync(0xffffffffu, q, o);
    __syncthreads();
    if (lane == 0) red[wid] = q;
    __syncthreads();
    float var = (red[0] + red[1] + red[2] + red[3]) * (1.0f / HH);
    float rstd = rsqrtf(var + 1e-5f);
    float y0 = d0 * rstd * lng[l * HH + ch0]     + lnb[l * HH + ch0];
    float y1 = d1 * rstd * lng[l * HH + ch0 + 1] + lnb[l * HH + ch0 + 1];
    *(float2*)&g_h[n * HH + ch0] = make_float2(fmaxf(y0, 0.f), fmaxf(y1, 0.f));
}

// graph pooling + value head + Potts energy
__global__ void k_graph(const float* __restrict__ v1W, const float* __restrict__ v1b,
                        const float* __restrict__ v2W, const float* __restrict__ v2b,
                        const float* __restrict__ coup, float* __restrict__ out,
                        int N, long long P) {
    __shared__ float gr[2 * HH];
    __shared__ float psum[2][HH];
    __shared__ float pmax[2][HH];
    __shared__ float sred[512];
    int t = threadIdx.x;
    int half = t >> 8, ch = t & 255;
    int nh = N >> 1;
    {
        float s = 0.f, mx = -1e30f;
        for (int n = half * nh; n < (half + 1) * nh; n++) {
            float v = g_h[n * HH + ch];
            s += v; mx = fmaxf(mx, v);
        }
        psum[half][ch] = s; pmax[half][ch] = mx;
    }
    __syncthreads();
    if (t < HH) {
        gr[t] = (psum[0][t] + psum[1][t]) / (float)N;
        gr[HH + t] = fmaxf(pmax[0][t], pmax[1][t]);
    }
    __syncthreads();
    float contrib = 0.f;
    if (t < HH) {
        float a = v1b[t];
        for (int c = 0; c < 2 * HH; c++) a = fmaf(gr[c], v1W[c * HH + t], a);
        a = fmaxf(a, 0.f);
        contrib = a * v2W[t];
    }
    sred[t] = contrib;
    __syncthreads();
    for (int off = 256; off > 0; off >>= 1) {
        if (t < off) sred[t] += sred[t + off];
        __syncthreads();
    }
    if (t == 0) out[P] = sred[0] + v2b[0];

    float e = 0.f;
    for (int n = t; n < N; n += 512) {
        float d1 = (float)g_deg1[n], d2 = (float)g_deg2[n];
        e += d1 * d1 + d2 * d2;
    }
    __syncthreads();
    sred[t] = e;
    __syncthreads();
    for (int off = 256; off > 0; off >>= 1) {
        if (t < off) sred[t] += sred[t + off];
        __syncthreads();
    }
    if (t == 0) out[P + 1] = coup[0] * sred[0] / (2.0f * (float)N);
}

// A = h @ p1_W[:H] + p1_b,  B = h @ p1_W[H:]   (factorized pair-MLP layer 1)
__global__ void __launch_bounds__(128)
k_AB(const float* __restrict__ p1W, const float* __restrict__ p1b, int N) {
    __shared__ float hr[NLN][HH];
    __shared__ float wbuf[2][2][NLC][128];
    int nb = blockIdx.x * NLN;
    int chb = blockIdx.y * 128;
    int t = threadIdx.x;
    int ch = chb + t;
    for (int idx = t; idx < NLN * HH; idx += 128) {
        int r = idx >> 8, c = idx & 255;
        int n = nb + r;
        hr[r][c] = (n < N) ? g_h[n * HH + c] : 0.f;
    }
    const float* WA = p1W + chb;                   // rows 0..255
    const float* WB = p1W + (size_t)HH * HH + chb; // rows 256..511
#pragma unroll
    for (int r = 0; r < NLC; r++) {
        wbuf[0][0][r][t] = WA[r * HH + t];
        wbuf[0][1][r][t] = WB[r * HH + t];
    }
    float a[NLN], b[NLN];
    float bv = p1b[ch];
#pragma unroll
    for (int r = 0; r < NLN; r++) { a[r] = bv; b[r] = 0.f; }
    const int nch = HH / NLC;
    for (int k = 0; k < nch; k++) {
        int buf = k & 1;
        __syncthreads();
        if (k + 1 < nch) {
            int c0 = (k + 1) * NLC;
#pragma unroll
            for (int r = 0; r < NLC; r++) {
                wbuf[buf ^ 1][0][r][t] = WA[(c0 + r) * HH + t];
                wbuf[buf ^ 1][1][r][t] = WB[(c0 + r) * HH + t];
            }
        }
#pragma unroll
        for (int r = 0; r < NLC; r++) {
            int c = k * NLC + r;
            float wt = wbuf[buf][0][r][t];
            float wb = wbuf[buf][1][r][t];
#pragma unroll
            for (int n = 0; n < NLN; n++) {
                a[n] = fmaf(hr[n][c], wt, a[n]);
                b[n] = fmaf(hr[n][c], wb, b[n]);
            }
        }
    }
#pragma unroll
    for (int r = 0; r < NLN; r++) {
        int n = nb + r;
        if (n < N) { g_A[n * HH + ch] = a[r]; g_B[n * HH + ch] = b[r]; }
    }
}

// fused all-pairs MLP body: q = relu(A[i]+B[j]); out2 = relu(q@W2+b2);
// logit = out2.w3+b3.  Shared by real kernel and the 8-block profiling probe.
#define PCHUNK 32
__device__ __forceinline__ void pairs_body(
        const float* __restrict__ p2W, const float* __restrict__ p2b,
        const float* __restrict__ p3W, const float* __restrict__ p3b,
        float* __restrict__ out, int N, long long P) {
    __shared__ unsigned long long qs2[128][PCHUNK];   // (q,q) duplicated
    __shared__ unsigned long long w2s[PCHUNK][64];    // packed weight pairs
    __shared__ int si[128], sj[128];
    int tid = threadIdx.x;
    int tx = tid & 15, ty = tid >> 4;
    long long pbase = (long long)blockIdx.x * 128;

    if (tid < 128) {
        long long p = pbase + tid;
        if (p > P - 1) p = P - 1;
        float tn = 2.0f * N - 1.0f;
        float disc = fmaxf(tn * tn - 8.0f * (float)p, 0.0f);
        int i = (int)((tn - sqrtf(disc)) * 0.5f);
        if (i < 0) i = 0;
        if (i > N - 2) i = N - 2;
        while ((long long)(i + 1) * (2 * N - 2 - i) / 2 <= p) i++;
        while ((long long)i * (2 * N - 1 - i) / 2 > p) i--;
        int j = i + 1 + (int)(p - (long long)i * (2 * N - 1 - i) / 2);
        si[tid] = i; sj[tid] = j;
    }

    unsigned long long acc[8][4] = {};
    for (int c0 = 0; c0 < HH; c0 += PCHUNK) {
        __syncthreads();
        for (int idx = tid; idx < 128 * PCHUNK; idx += 256) {
            int pr = idx >> 5, c = idx & 31;
            float q = g_A[si[pr] * HH + c0 + c] + g_B[sj[pr] * HH + c0 + c];
            q = q > 0.f ? q : 0.f;
            qs2[pr][c] = pk2(q, q);
        }
        for (int idx = tid; idx < PCHUNK * 64; idx += 256) {
            int c = idx >> 6, id = idx & 63;
            int k0 = (id & 15) + ((id >> 4) << 5);
            w2s[c][id] = pk2(p2W[(c0 + c) * 128 + k0],
                             p2W[(c0 + c) * 128 + k0 + 16]);
        }
        __syncthreads();
#pragma unroll 4
        for (int c = 0; c < PCHUNK; c++) {
            unsigned long long b2[4];
#pragma unroll
            for (int q = 0; q < 4; q++) b2[q] = w2s[c][tx + 16 * q];
#pragma unroll
            for (int r = 0; r < 8; r++) {
                unsigned long long a2 = qs2[ty + 16 * r][c];
#pragma unroll
                for (int q = 0; q < 4; q++) fma2(acc[r][q], a2, b2[q]);
            }
        }
    }

    float b3v = p3b[0];
#pragma unroll
    for (int r = 0; r < 8; r++) {
        float part = 0.f;
#pragma unroll
        for (int q = 0; q < 4; q++) {
            float v0, v1;
            upk2(acc[r][q], v0, v1);
            int k0 = tx + 32 * q, k1 = k0 + 16;
            v0 += p2b[k0]; v0 = fmaxf(v0, 0.f); part = fmaf(v0, p3W[k0], part);
            v1 += p2b[k1]; v1 = fmaxf(v1, 0.f); part = fmaf(v1, p3W[k1], part);
        }
#pragma unroll
        for (int o = 8; o > 0; o >>= 1)
            part += __shfl_xor_sync(0xffffffffu, part, o);
        if (tx == 0) {
            long long p = pbase + ty + 16 * r;
            if (p < P) out[p] = part + b3v;
        }
    }
}

__global__ void __launch_bounds__(256, 2)
k_pairs(const float* __restrict__ p2W, const float* __restrict__ p2b,
        const float* __restrict__ p3W, const float* __restrict__ p3b,
        float* __restrict__ out, int N, long long P) {
    pairs_body(p2W, p2b, p3W, p3b, out, N, P);
}

// 8-block probe: identical body, writes to a dummy device buffer (reads
// whatever g_A/g_B hold — deterministic across replays, output unused).
__global__ void __launch_bounds__(256, 2)
k_pairs_probe(const float* __restrict__ p2W, const float* __restrict__ p2b,
              const float* __restrict__ p3W, const float* __restrict__ p3b,
              int N, long long P) {
    pairs_body(p2W, p2b, p3W, p3b, g_dummy, N, 1024 < P ? 1024 : P);
}

// ---------------- launch ------------------------------------------------------
extern "C" void kernel_launch(void* const* d_in, const int* in_sizes, int n_in,
                              void* d_out, int out_size) {
    const float* x    = (const float*)d_in[0];
    const int*   ei   = (const int*)  d_in[1];
    const float* ea   = (const float*)d_in[2];
    const float* embW = (const float*)d_in[3];
    const float* embB = (const float*)d_in[4];
    const float* Wl   = (const float*)d_in[5];
    const float* bl   = (const float*)d_in[6];
    const float* Wr   = (const float*)d_in[7];
    const float* br   = (const float*)d_in[8];
    const float* We   = (const float*)d_in[9];
    const float* att  = (const float*)d_in[10];
    const float* gb   = (const float*)d_in[11];
    const float* lng  = (const float*)d_in[12];
    const float* lnb  = (const float*)d_in[13];
    const float* p1W  = (const float*)d_in[14];
    const float* p1b  = (const float*)d_in[15];
    const float* p2W  = (const float*)d_in[16];
    const float* p2b  = (const float*)d_in[17];
    const float* p3W  = (const float*)d_in[18];
    const float* p3b  = (const float*)d_in[19];
    const float* v1W  = (const float*)d_in[20];
    const float* v1b  = (const float*)d_in[21];
    const float* v2W  = (const float*)d_in[22];
    const float* v2b  = (const float*)d_in[23];
    const float* coup = (const float*)d_in[24];

    int N = in_sizes[0];
    int E = in_sizes[1] / 2;
    long long P = (long long)N * (N - 1) / 2;
    float* out = (float*)d_out;

    dim3 nl((N + NLN - 1) / NLN, 2);
    // order: probe lands in the profiler's fixed capture slot (4th launch)
    k_embinit<<<N, 256>>>(x, embW, embB);
    k_edge_stats<<<(E + 255) / 256, 256>>>(ei, ea, E);
    k_nodelin<<<nl, 128>>>(Wl, bl, Wr, br, 0, N);
    k_pairs_probe<<<8, 256>>>(p2W, p2b, p3W, p3b, N, P);
    k_scan<<<1, 1024>>>(N);
    k_scatter<<<(E + 255) / 256, 256>>>(ei, ea, E);
    k_gat<<<N, 128>>>(We, att, gb, lng, lnb, 0);
    for (int l = 1; l < 4; l++) {
        k_nodelin<<<nl, 128>>>(Wl, bl, Wr, br, l, N);
        k_gat<<<N, 128>>>(We, att, gb, lng, lnb, l);
    }
    k_graph<<<1, 512>>>(v1W, v1b, v2W, v2b, coup, out, N, P);
    k_AB<<<nl, 128>>>(p1W, p1b, N);
    int pblocks = (int)((P + 127) / 128);
    k_pairs<<<pblocks, 256>>>(p2W, p2b, p3W, p3b, out, N, P);
}

// round 7
// speedup vs baseline: 1.0509x; 1.0509x over previous
#include <cuda_runtime.h>
#include <math.h>

#define HH       256
#define NHEADS   8
#define MAX_N    1024
#define MAX_EDGES 600000
#define ETILE    256
#define SUB      32

// ---------------- scratch (device globals; no allocation allowed) -------------
__device__ int    g_cnt2[MAX_N * SUB];
__device__ int    g_cur2[MAX_N * SUB];
__device__ int    g_roff[MAX_N + 1];
__device__ int    g_deg1[MAX_N];
__device__ int    g_deg2[MAX_N];
__device__ float  g_asum[MAX_N * 3];
__device__ float4 g_epack[MAX_EDGES];          // (src_as_float, a0, a1, a2)
__device__ float  g_h [MAX_N * HH];
__device__ float  g_xl[MAX_N * HH];
__device__ float  g_xr[MAX_N * HH];
__device__ float  g_A [MAX_N * HH];
__device__ float  g_B [MAX_N * HH];

// ---------------- f32x2 packed helpers (bit-exact fp32, 2x FFMA tput) ---------
__device__ __forceinline__ unsigned long long pk2(float a, float b) {
    unsigned long long r;
    asm("mov.b64 %0, {%1,%2};" : "=l"(r) : "f"(a), "f"(b));
    return r;
}
__device__ __forceinline__ void upk2(unsigned long long v, float& a, float& b) {
    asm("mov.b64 {%0,%1}, %2;" : "=f"(a), "=f"(b) : "l"(v));
}
__device__ __forceinline__ void fma2(unsigned long long& d, unsigned long long a,
                                     unsigned long long b) {
    asm("fma.rn.f32x2 %0, %1, %2, %0;" : "+l"(d) : "l"(a), "l"(b));
}

// ---------------- setup kernels ------------------------------------------------
// embedding + per-node scratch init fused (block n handles node n)
__global__ void k_embinit(const float* __restrict__ x, const float* __restrict__ W,
                          const float* __restrict__ b) {
    int n = blockIdx.x, t = threadIdx.x;
    g_h[n * HH + t] = x[n] * W[t] + b[t];
    if (t < SUB) g_cnt2[n * SUB + t] = 0;
    if (t == 32) { g_deg1[n] = 0; g_deg2[n] = 0; }
    if (t == 33) {
        g_asum[3 * n] = 0.f; g_asum[3 * n + 1] = 0.f; g_asum[3 * n + 2] = 0.f;
    }
}

__global__ void k_edge_stats(const int* __restrict__ ei, const float* __restrict__ ea,
                             int E) {
    int e = blockIdx.x * blockDim.x + threadIdx.x;
    if (e >= E) return;
    int s = ei[e], d = ei[E + e];
    float a0 = ea[3 * e], a1 = ea[3 * e + 1], a2 = ea[3 * e + 2];
    atomicAdd(&g_cnt2[d * SUB + (e & (SUB - 1))], 1);     // RED, no return
    atomicAdd(&g_asum[3 * d + 0], a0);
    atomicAdd(&g_asum[3 * d + 1], a1);
    atomicAdd(&g_asum[3 * d + 2], a2);
    // argmax with first-occurrence ties (matches jnp.argmax)
    int best = 0; float bv = a0;
    if (a1 > bv) { best = 1; bv = a1; }
    if (a2 > bv) { best = 2; }
    if (best == 1) { atomicAdd(&g_deg1[s], 1); atomicAdd(&g_deg1[d], 1); }
    else if (best == 2) { atomicAdd(&g_deg2[s], 1); atomicAdd(&g_deg2[d], 1); }
}

// prefix scan of segment lengths (cnt+1 for self-loop), sub-bucket bases,
// and self-loop packed entry
__global__ void k_scan(int N) {
    __shared__ int sc[1024];
    int t = threadIdx.x;
    int subc[SUB];
    int cnt = 0;
    if (t < N) {
#pragma unroll
        for (int s = 0; s < SUB; s++) { subc[s] = g_cnt2[t * SUB + s]; cnt += subc[s]; }
    }
    int len = (t < N) ? (cnt + 1) : 0;
    sc[t] = len;
    __syncthreads();
    for (int off = 1; off < 1024; off <<= 1) {
        int v = (t >= off) ? sc[t - off] : 0;
        __syncthreads();
        sc[t] += v;
        __syncthreads();
    }
    if (t < N) {
        int incl = sc[t];
        int excl = incl - len;
        g_roff[t + 1] = incl;
        if (t == 0) g_roff[0] = 0;
        int off = excl;
#pragma unroll
        for (int s = 0; s < SUB; s++) { g_cur2[t * SUB + s] = off; off += subc[s]; }
        int slot = excl + cnt;                     // self-loop at end of segment
        float c = fmaxf((float)cnt, 1.0f);
        g_epack[slot] = make_float4(__int_as_float(t),
                                    g_asum[3 * t + 0] / c,
                                    g_asum[3 * t + 1] / c,
                                    g_asum[3 * t + 2] / c);
    }
}

__global__ void k_scatter(const int* __restrict__ ei, const float* __restrict__ ea,
                          int E) {
    int e = blockIdx.x * blockDim.x + threadIdx.x;
    if (e >= E) return;
    int s = ei[e], d = ei[E + e];
    int pos = atomicAdd(&g_cur2[d * SUB + (e & (SUB - 1))], 1);
    g_epack[pos] = make_float4(__int_as_float(s), ea[3 * e], ea[3 * e + 1], ea[3 * e + 2]);
}

// xl = h@Wl + bl ; xr = h@Wr + br
// block = 4 nodes x 128 channels, weights double-buffered through smem
#define NLN 4
#define NLC 16
__global__ void __launch_bounds__(128)
k_nodelin(const float* __restrict__ Wl, const float* __restrict__ bl,
          const float* __restrict__ Wr, const float* __restrict__ br,
          int l, int N) {
    __shared__ float hr[NLN][HH];
    __shared__ float wbuf[2][2][NLC][128];
    int nb = blockIdx.x * NLN;
    int chb = blockIdx.y * 128;
    int t = threadIdx.x;
    int ch = chb + t;
    for (int idx = t; idx < NLN * HH; idx += 128) {
        int r = idx >> 8, c = idx & 255;
        int n = nb + r;
        hr[r][c] = (n < N) ? g_h[n * HH + c] : 0.f;
    }
    const float* WL = Wl + (size_t)l * HH * HH + chb;
    const float* WR = Wr + (size_t)l * HH * HH + chb;
#pragma unroll
    for (int r = 0; r < NLC; r++) {
        wbuf[0][0][r][t] = WL[r * HH + t];
        wbuf[0][1][r][t] = WR[r * HH + t];
    }
    float aL[NLN], aR[NLN];
    float blv = bl[l * HH + ch], brv = br[l * HH + ch];
#pragma unroll
    for (int r = 0; r < NLN; r++) { aL[r] = blv; aR[r] = brv; }
    const int nch = HH / NLC;
    for (int k = 0; k < nch; k++) {
        int buf = k & 1;
        __syncthreads();
        if (k + 1 < nch) {
            int c0 = (k + 1) * NLC;
#pragma unroll
            for (int r = 0; r < NLC; r++) {
                wbuf[buf ^ 1][0][r][t] = WL[(c0 + r) * HH + t];
                wbuf[buf ^ 1][1][r][t] = WR[(c0 + r) * HH + t];
            }
        }
#pragma unroll
        for (int r = 0; r < NLC; r++) {
            int c = k * NLC + r;
            float wl = wbuf[buf][0][r][t];
            float wr = wbuf[buf][1][r][t];
#pragma unroll
            for (int n = 0; n < NLN; n++) {
                aL[n] = fmaf(hr[n][c], wl, aL[n]);
                aR[n] = fmaf(hr[n][c], wr, aR[n]);
            }
        }
    }
#pragma unroll
    for (int r = 0; r < NLN; r++) {
        int n = nb + r;
        if (n < N) { g_xl[n * HH + ch] = aL[r]; g_xr[n * HH + ch] = aR[r]; }
    }
}

// one block (128 threads, float2/thread) per destination node: fused GATv2
// scoring + softmax + aggregation + residual + LayerNorm + ReLU.
// No running max (scores O(0.05) -> exp() safe): every 4-edge group is fully
// independent, no serial rescale chain.
__global__ void __launch_bounds__(128)
k_gat(const float* __restrict__ We, const float* __restrict__ att,
      const float* __restrict__ gb, const float* __restrict__ lng,
      const float* __restrict__ lnb, int l) {
    __shared__ float4 ep[ETILE];
    __shared__ float red[4];
    int n = blockIdx.x, t = threadIdx.x;
    int wid = t >> 5, lane = t & 31;
    int ch0 = 2 * t;
    int head = t >> 4;
    int hc = ch0 & 31;
    float2 xr2 = *(const float2*)&g_xr[n * HH + ch0];
    float2 hres = *(const float2*)&g_h[n * HH + ch0];
    float att0 = att[(l * NHEADS + head) * 32 + hc];
    float att1 = att[(l * NHEADS + head) * 32 + hc + 1];
    float we00 = We[(l * 3 + 0) * HH + ch0], we01 = We[(l * 3 + 0) * HH + ch0 + 1];
    float we10 = We[(l * 3 + 1) * HH + ch0], we11 = We[(l * 3 + 1) * HH + ch0 + 1];
    float we20 = We[(l * 3 + 2) * HH + ch0], we21 = We[(l * 3 + 2) * HH + ch0 + 1];
    int e0 = g_roff[n], e1 = g_roff[n + 1];

    float den = 0.f, acc0 = 0.f, acc1 = 0.f;
    for (int t0 = e0; t0 < e1; t0 += ETILE) {
        int cnt = min(ETILE, e1 - t0);
        __syncthreads();
        for (int k = t; k < cnt; k += 128) ep[k] = g_epack[t0 + k];
        __syncthreads();
#pragma unroll 2
        for (int g = 0; g < cnt; g += 4) {
            float2 xv[4];
            float al[4];
#pragma unroll
            for (int u = 0; u < 4; u++) {
                int idx = min(g + u, cnt - 1);
                float4 e = ep[idx];
                int s = __float_as_int(e.x);
                xv[u] = *(const float2*)&g_xl[s * HH + ch0];
                float s0 = xv[u].x + xr2.x + e.y * we00 + e.z * we10 + e.w * we20;
                float s1 = xv[u].y + xr2.y + e.y * we01 + e.z * we11 + e.w * we21;
                s0 = s0 > 0.f ? s0 : 0.2f * s0;
                s1 = s1 > 0.f ? s1 : 0.2f * s1;
                float v = s0 * att0 + s1 * att1;
                al[u] = (g + u < cnt) ? v : -1e30f;
            }
            // multi-reduce: 4 head-sums over 16-lane groups in 5 shfls
            float p0 = (lane & 8) ? al[2] : al[0];
            float q0 = (lane & 8) ? al[0] : al[2];
            float p1 = (lane & 8) ? al[3] : al[1];
            float q1 = (lane & 8) ? al[1] : al[3];
            p0 += __shfl_xor_sync(0xffffffffu, q0, 8);
            p1 += __shfl_xor_sync(0xffffffffu, q1, 8);
            float pa = (lane & 4) ? p1 : p0;
            float qa = (lane & 4) ? p0 : p1;
            pa += __shfl_xor_sync(0xffffffffu, qa, 4);
            pa += __shfl_xor_sync(0xffffffffu, pa, 2);
            pa += __shfl_xor_sync(0xffffffffu, pa, 1);
            int base = lane & 16;
#pragma unroll
            for (int u = 0; u < 4; u++) {
                float w = __expf(__shfl_sync(0xffffffffu, pa, base + (u << 2)));
                den += w;
                acc0 = fmaf(w, xv[u].x, acc0);
                acc1 = fmaf(w, xv[u].y, acc1);
            }
        }
    }
    float inv = 1.0f / den;
    float o0 = acc0 * inv + gb[l * HH + ch0]     + hres.x;
    float o1 = acc1 * inv + gb[l * HH + ch0 + 1] + hres.y;

    // LayerNorm over 256 channels (block reduce over 4 warps), then ReLU
    float v = o0 + o1;
#pragma unroll
    for (int o = 16; o > 0; o >>= 1) v += __shfl_xor_sync(0xffffffffu, v, o);
    if (lane == 0) red[wid] = v;
    __syncthreads();
    float mu = (red[0] + red[1] + red[2] + red[3]) * (1.0f / HH);
    float d0 = o0 - mu, d1 = o1 - mu;
    float q = d0 * d0 + d1 * d1;
#pragma unroll
    for (int o = 16; o > 0; o >>= 1) q += __shfl_xor_sync(0xffffffffu, q, o);
    __syncthreads();
    if (lane == 0) red[wid] = q;
    __syncthreads();
    float var = (red[0] + red[1] + red[2] + red[3]) * (1.0f / HH);
    float rstd = rsqrtf(var + 1e-5f);
    float y0 = d0 * rstd * lng[l * HH + ch0]     + lnb[l * HH + ch0];
    float y1 = d1 * rstd * lng[l * HH + ch0 + 1] + lnb[l * HH + ch0 + 1];
    *(float2*)&g_h[n * HH + ch0] = make_float2(fmaxf(y0, 0.f), fmaxf(y1, 0.f));
}

// graph pooling + value head + Potts energy
__global__ void k_graph(const float* __restrict__ v1W, const float* __restrict__ v1b,
                        const float* __restrict__ v2W, const float* __restrict__ v2b,
                        const float* __restrict__ coup, float* __restrict__ out,
                        int N, long long P) {
    __shared__ float gr[2 * HH];
    __shared__ float psum[2][HH];
    __shared__ float pmax[2][HH];
    __shared__ float sred[512];
    int t = threadIdx.x;
    int half = t >> 8, ch = t & 255;
    int nh = N >> 1;
    {
        float s = 0.f, mx = -1e30f;
        for (int n = half * nh; n < (half + 1) * nh; n++) {
            float v = g_h[n * HH + ch];
            s += v; mx = fmaxf(mx, v);
        }
        psum[half][ch] = s; pmax[half][ch] = mx;
    }
    __syncthreads();
    if (t < HH) {
        gr[t] = (psum[0][t] + psum[1][t]) / (float)N;
        gr[HH + t] = fmaxf(pmax[0][t], pmax[1][t]);
    }
    __syncthreads();
    float contrib = 0.f;
    if (t < HH) {
        float a = v1b[t];
        for (int c = 0; c < 2 * HH; c++) a = fmaf(gr[c], v1W[c * HH + t], a);
        a = fmaxf(a, 0.f);
        contrib = a * v2W[t];
    }
    sred[t] = contrib;
    __syncthreads();
    for (int off = 256; off > 0; off >>= 1) {
        if (t < off) sred[t] += sred[t + off];
        __syncthreads();
    }
    if (t == 0) out[P] = sred[0] + v2b[0];

    float e = 0.f;
    for (int n = t; n < N; n += 512) {
        float d1 = (float)g_deg1[n], d2 = (float)g_deg2[n];
        e += d1 * d1 + d2 * d2;
    }
    __syncthreads();
    sred[t] = e;
    __syncthreads();
    for (int off = 256; off > 0; off >>= 1) {
        if (t < off) sred[t] += sred[t + off];
        __syncthreads();
    }
    if (t == 0) out[P + 1] = coup[0] * sred[0] / (2.0f * (float)N);
}

// A = h @ p1_W[:H] + p1_b,  B = h @ p1_W[H:]   (factorized pair-MLP layer 1)
__global__ void __launch_bounds__(128)
k_AB(const float* __restrict__ p1W, const float* __restrict__ p1b, int N) {
    __shared__ float hr[NLN][HH];
    __shared__ float wbuf[2][2][NLC][128];
    int nb = blockIdx.x * NLN;
    int chb = blockIdx.y * 128;
    int t = threadIdx.x;
    int ch = chb + t;
    for (int idx = t; idx < NLN * HH; idx += 128) {
        int r = idx >> 8, c = idx & 255;
        int n = nb + r;
        hr[r][c] = (n < N) ? g_h[n * HH + c] : 0.f;
    }
    const float* WA = p1W + chb;                   // rows 0..255
    const float* WB = p1W + (size_t)HH * HH + chb; // rows 256..511
#pragma unroll
    for (int r = 0; r < NLC; r++) {
        wbuf[0][0][r][t] = WA[r * HH + t];
        wbuf[0][1][r][t] = WB[r * HH + t];
    }
    float a[NLN], b[NLN];
    float bv = p1b[ch];
#pragma unroll
    for (int r = 0; r < NLN; r++) { a[r] = bv; b[r] = 0.f; }
    const int nch = HH / NLC;
    for (int k = 0; k < nch; k++) {
        int buf = k & 1;
        __syncthreads();
        if (k + 1 < nch) {
            int c0 = (k + 1) * NLC;
#pragma unroll
            for (int r = 0; r < NLC; r++) {
                wbuf[buf ^ 1][0][r][t] = WA[(c0 + r) * HH + t];
                wbuf[buf ^ 1][1][r][t] = WB[(c0 + r) * HH + t];
            }
        }
#pragma unroll
        for (int r = 0; r < NLC; r++) {
            int c = k * NLC + r;
            float wt = wbuf[buf][0][r][t];
            float wb = wbuf[buf][1][r][t];
#pragma unroll
            for (int n = 0; n < NLN; n++) {
                a[n] = fmaf(hr[n][c], wt, a[n]);
                b[n] = fmaf(hr[n][c], wb, b[n]);
            }
        }
    }
#pragma unroll
    for (int r = 0; r < NLN; r++) {
        int n = nb + r;
        if (n < N) { g_A[n * HH + ch] = a[r]; g_B[n * HH + ch] = b[r]; }
    }
}

// fused all-pairs MLP: q = relu(A[i]+B[j]); out2 = relu(q@W2+b2); logit=out2.w3+b3
// 512 threads: ty(0..15)+16r covers 128 pairs, tx(0..31) covers 128 outputs as
// 2 u64. acc[8][2] = 32 regs (was 64 -> reg-cap spills). K chunked by 16.
#define PCH 16
__global__ void __launch_bounds__(512, 2)
k_pairs(const float* __restrict__ p2W, const float* __restrict__ p2b,
        const float* __restrict__ p3W, const float* __restrict__ p3b,
        float* __restrict__ out, int N, long long P) {
    __shared__ unsigned long long qs2[128][PCH];   // (q,q) duplicated  16KB
    __shared__ unsigned long long w2s[PCH][64];    // packed weight pairs 8KB
    __shared__ int si[128], sj[128];
    int tid = threadIdx.x;
    int tx = tid & 31, ty = tid >> 5;
    long long pbase = (long long)blockIdx.x * 128;

    if (tid < 128) {
        long long p = pbase + tid;
        if (p > P - 1) p = P - 1;
        float tn = 2.0f * N - 1.0f;
        float disc = fmaxf(tn * tn - 8.0f * (float)p, 0.0f);
        int i = (int)((tn - sqrtf(disc)) * 0.5f);
        if (i < 0) i = 0;
        if (i > N - 2) i = N - 2;
        while ((long long)(i + 1) * (2 * N - 2 - i) / 2 <= p) i++;
        while ((long long)i * (2 * N - 1 - i) / 2 > p) i--;
        int j = i + 1 + (int)(p - (long long)i * (2 * N - 1 - i) / 2);
        si[tid] = i; sj[tid] = j;
    }

    unsigned long long acc[8][2] = {};
    for (int c0 = 0; c0 < HH; c0 += PCH) {
        __syncthreads();
        for (int idx = tid; idx < 128 * PCH; idx += 512) {
            int pr = idx >> 4, c = idx & 15;
            float q = g_A[si[pr] * HH + c0 + c] + g_B[sj[pr] * HH + c0 + c];
            q = q > 0.f ? q : 0.f;
            qs2[pr][c] = pk2(q, q);
        }
        for (int idx = tid; idx < PCH * 64; idx += 512) {
            int c = idx >> 6, id = idx & 63;
            int kq = id >> 5, kt = id & 31;
            w2s[c][id] = pk2(p2W[(c0 + c) * 128 + kt + 64 * kq],
                             p2W[(c0 + c) * 128 + kt + 64 * kq + 32]);
        }
        __syncthreads();
#pragma unroll 4
        for (int c = 0; c < PCH; c++) {
            unsigned long long b0 = w2s[c][tx];
            unsigned long long b1 = w2s[c][tx + 32];
#pragma unroll
            for (int r = 0; r < 8; r++) {
                unsigned long long a2 = qs2[ty + 16 * r][c];
                fma2(acc[r][0], a2, b0);
                fma2(acc[r][1], a2, b1);
            }
        }
    }

    // epilogue: k indices for this thread: q=0 -> (tx, tx+32); q=1 -> (tx+64, tx+96)
    float bb0 = p2b[tx],      bb1 = p2b[tx + 32];
    float bb2 = p2b[tx + 64], bb3 = p2b[tx + 96];
    float w30 = p3W[tx],      w31 = p3W[tx + 32];
    float w32 = p3W[tx + 64], w33 = p3W[tx + 96];
    float b3v = p3b[0];
#pragma unroll
    for (int r = 0; r < 8; r++) {
        float v0, v1, v2, v3;
        upk2(acc[r][0], v0, v1);
        upk2(acc[r][1], v2, v3);
        float part = 0.f;
        part = fmaf(fmaxf(v0 + bb0, 0.f), w30, part);
        part = fmaf(fmaxf(v1 + bb1, 0.f), w31, part);
        part = fmaf(fmaxf(v2 + bb2, 0.f), w32, part);
        part = fmaf(fmaxf(v3 + bb3, 0.f), w33, part);
#pragma unroll
        for (int o = 16; o > 0; o >>= 1)
            part += __shfl_xor_sync(0xffffffffu, part, o);
        if (tx == 0) {
            long long p = pbase + ty + 16 * r;
            if (p < P) out[p] = part + b3v;
        }
    }
}

// ---------------- launch ------------------------------------------------------
extern "C" void kernel_launch(void* const* d_in, const int* in_sizes, int n_in,
                              void* d_out, int out_size) {
    const float* x    = (const float*)d_in[0];
    const int*   ei   = (const int*)  d_in[1];
    const float* ea   = (const float*)d_in[2];
    const float* embW = (const float*)d_in[3];
    const float* embB = (const float*)d_in[4];
    const float* Wl   = (const float*)d_in[5];
    const float* bl   = (const float*)d_in[6];
    const float* Wr   = (const float*)d_in[7];
    const float* br   = (const float*)d_in[8];
    const float* We   = (const float*)d_in[9];
    const float* att  = (const float*)d_in[10];
    const float* gb   = (const float*)d_in[11];
    const float* lng  = (const float*)d_in[12];
    const float* lnb  = (const float*)d_in[13];
    const float* p1W  = (const float*)d_in[14];
    const float* p1b  = (const float*)d_in[15];
    const float* p2W  = (const float*)d_in[16];
    const float* p2b  = (const float*)d_in[17];
    const float* p3W  = (const float*)d_in[18];
    const float* p3b  = (const float*)d_in[19];
    const float* v1W  = (const float*)d_in[20];
    const float* v1b  = (const float*)d_in[21];
    const float* v2W  = (const float*)d_in[22];
    const float* v2b  = (const float*)d_in[23];
    const float* coup = (const float*)d_in[24];

    int N = in_sizes[0];
    int E = in_sizes[1] / 2;
    long long P = (long long)N * (N - 1) / 2;
    float* out = (float*)d_out;

    dim3 nl((N + NLN - 1) / NLN, 2);
    k_embinit<<<N, 256>>>(x, embW, embB);
    k_edge_stats<<<(E + 255) / 256, 256>>>(ei, ea, E);
    k_nodelin<<<nl, 128>>>(Wl, bl, Wr, br, 0, N);
    k_scan<<<1, 1024>>>(N);
    k_scatter<<<(E + 255) / 256, 256>>>(ei, ea, E);
    k_gat<<<N, 128>>>(We, att, gb, lng, lnb, 0);
    for (int l = 1; l < 4; l++) {
        k_nodelin<<<nl, 128>>>(Wl, bl, Wr, br, l, N);
        k_gat<<<N, 128>>>(We, att, gb, lng, lnb, l);
    }
    k_graph<<<1, 512>>>(v1W, v1b, v2W, v2b, coup, out, N, P);
    k_AB<<<nl, 128>>>(p1W, p1b, N);
    int pblocks = (int)((P + 127) / 128);
    k_pairs<<<pblocks, 512>>>(p2W, p2b, p3W, p3b, out, N, P);
}

// round 8
// speedup vs baseline: 1.0586x; 1.0074x over previous
#include <cuda_runtime.h>
#include <math.h>

#define HH       256
#define NHEADS   8
#define MAX_N    1024
#define MAX_EDGES 600000
#define ETILE    256
#define SUB      32

// ---------------- scratch (device globals; no allocation allowed) -------------
__device__ __align__(16) int    g_cnt2[MAX_N * SUB];
__device__ __align__(16) int    g_cur2[MAX_N * SUB];
__device__ int    g_roff[MAX_N + 1];
__device__ int    g_deg1[MAX_N];
__device__ int    g_deg2[MAX_N];
__device__ float  g_asum[MAX_N * 3];
__device__ float4 g_epack[MAX_EDGES];          // (src_as_float, a0, a1, a2)
__device__ float  g_h [MAX_N * HH];
__device__ float  g_xl[MAX_N * HH];
__device__ float  g_xr[MAX_N * HH];
__device__ float  g_A [MAX_N * HH];
__device__ float  g_B [MAX_N * HH];

// ---------------- f32x2 packed helpers (bit-exact fp32, 2x FFMA tput) ---------
__device__ __forceinline__ unsigned long long pk2(float a, float b) {
    unsigned long long r;
    asm("mov.b64 %0, {%1,%2};" : "=l"(r) : "f"(a), "f"(b));
    return r;
}
__device__ __forceinline__ void upk2(unsigned long long v, float& a, float& b) {
    asm("mov.b64 {%0,%1}, %2;" : "=f"(a), "=f"(b) : "l"(v));
}
__device__ __forceinline__ void fma2(unsigned long long& d, unsigned long long a,
                                     unsigned long long b) {
    asm("fma.rn.f32x2 %0, %1, %2, %0;" : "+l"(d) : "l"(a), "l"(b));
}

// ---------------- setup kernels ------------------------------------------------
// embedding + per-node scratch init fused (block n handles node n)
__global__ void k_embinit(const float* __restrict__ x, const float* __restrict__ W,
                          const float* __restrict__ b) {
    int n = blockIdx.x, t = threadIdx.x;
    g_h[n * HH + t] = x[n] * W[t] + b[t];
    if (t < SUB) g_cnt2[n * SUB + t] = 0;
    if (t == 32) { g_deg1[n] = 0; g_deg2[n] = 0; }
    if (t == 33) {
        g_asum[3 * n] = 0.f; g_asum[3 * n + 1] = 0.f; g_asum[3 * n + 2] = 0.f;
    }
}

__global__ void k_edge_stats(const int* __restrict__ ei, const float* __restrict__ ea,
                             int E) {
    int e = blockIdx.x * blockDim.x + threadIdx.x;
    if (e >= E) return;
    int s = ei[e], d = ei[E + e];
    float a0 = ea[3 * e], a1 = ea[3 * e + 1], a2 = ea[3 * e + 2];
    atomicAdd(&g_cnt2[d * SUB + (e & (SUB - 1))], 1);     // RED, no return
    atomicAdd(&g_asum[3 * d + 0], a0);
    atomicAdd(&g_asum[3 * d + 1], a1);
    atomicAdd(&g_asum[3 * d + 2], a2);
    // argmax with first-occurrence ties (matches jnp.argmax)
    int best = 0; float bv = a0;
    if (a1 > bv) { best = 1; bv = a1; }
    if (a2 > bv) { best = 2; }
    if (best == 1) { atomicAdd(&g_deg1[s], 1); atomicAdd(&g_deg1[d], 1); }
    else if (best == 2) { atomicAdd(&g_deg2[s], 1); atomicAdd(&g_deg2[d], 1); }
}

// prefix scan of segment lengths (cnt+1 for self-loop), sub-bucket bases,
// and self-loop packed entry.  counters loaded as 8 independent LDG.128.
__global__ void k_scan(int N) {
    __shared__ int sc[1024];
    int t = threadIdx.x;
    int4 v[8];
    int cnt = 0;
    if (t < N) {
        const int4* p = (const int4*)(g_cnt2 + t * SUB);
#pragma unroll
        for (int i = 0; i < 8; i++) v[i] = p[i];
#pragma unroll
        for (int i = 0; i < 8; i++) cnt += v[i].x + v[i].y + v[i].z + v[i].w;
    }
    int len = (t < N) ? (cnt + 1) : 0;
    sc[t] = len;
    __syncthreads();
    for (int off = 1; off < 1024; off <<= 1) {
        int u = (t >= off) ? sc[t - off] : 0;
        __syncthreads();
        sc[t] += u;
        __syncthreads();
    }
    if (t < N) {
        int incl = sc[t];
        int excl = incl - len;
        g_roff[t + 1] = incl;
        if (t == 0) g_roff[0] = 0;
        int off = excl;
        int4* q = (int4*)(g_cur2 + t * SUB);
#pragma unroll
        for (int i = 0; i < 8; i++) {
            int4 o;
            o.x = off; off += v[i].x;
            o.y = off; off += v[i].y;
            o.z = off; off += v[i].z;
            o.w = off; off += v[i].w;
            q[i] = o;
        }
        int slot = excl + cnt;                     // self-loop at end of segment
        float c = fmaxf((float)cnt, 1.0f);
        g_epack[slot] = make_float4(__int_as_float(t),
                                    g_asum[3 * t + 0] / c,
                                    g_asum[3 * t + 1] / c,
                                    g_asum[3 * t + 2] / c);
    }
}

__global__ void k_scatter(const int* __restrict__ ei, const float* __restrict__ ea,
                          int E) {
    int e = blockIdx.x * blockDim.x + threadIdx.x;
    if (e >= E) return;
    int s = ei[e], d = ei[E + e];
    int pos = atomicAdd(&g_cur2[d * SUB + (e & (SUB - 1))], 1);
    g_epack[pos] = make_float4(__int_as_float(s), ea[3 * e], ea[3 * e + 1], ea[3 * e + 2]);
}

// xl = h@Wl + bl ; xr = h@Wr + br
// block = 2 nodes x 128 channels (512 blocks -> 3.5/SM), weights double-buffered
#define NLN 2
#define NLC 16
__global__ void __launch_bounds__(128)
k_nodelin(const float* __restrict__ Wl, const float* __restrict__ bl,
          const float* __restrict__ Wr, const float* __restrict__ br,
          int l, int N) {
    __shared__ float hr[NLN][HH];
    __shared__ float wbuf[2][2][NLC][128];
    int nb = blockIdx.x * NLN;
    int chb = blockIdx.y * 128;
    int t = threadIdx.x;
    int ch = chb + t;
    for (int idx = t; idx < NLN * HH; idx += 128) {
        int r = idx >> 8, c = idx & 255;
        int n = nb + r;
        hr[r][c] = (n < N) ? g_h[n * HH + c] : 0.f;
    }
    const float* WL = Wl + (size_t)l * HH * HH + chb;
    const float* WR = Wr + (size_t)l * HH * HH + chb;
#pragma unroll
    for (int r = 0; r < NLC; r++) {
        wbuf[0][0][r][t] = WL[r * HH + t];
        wbuf[0][1][r][t] = WR[r * HH + t];
    }
    float aL[NLN], aR[NLN];
    float blv = bl[l * HH + ch], brv = br[l * HH + ch];
#pragma unroll
    for (int r = 0; r < NLN; r++) { aL[r] = blv; aR[r] = brv; }
    const int nch = HH / NLC;
    for (int k = 0; k < nch; k++) {
        int buf = k & 1;
        __syncthreads();
        if (k + 1 < nch) {
            int c0 = (k + 1) * NLC;
#pragma unroll
            for (int r = 0; r < NLC; r++) {
                wbuf[buf ^ 1][0][r][t] = WL[(c0 + r) * HH + t];
                wbuf[buf ^ 1][1][r][t] = WR[(c0 + r) * HH + t];
            }
        }
#pragma unroll
        for (int r = 0; r < NLC; r++) {
            int c = k * NLC + r;
            float wl = wbuf[buf][0][r][t];
            float wr = wbuf[buf][1][r][t];
#pragma unroll
            for (int n = 0; n < NLN; n++) {
                aL[n] = fmaf(hr[n][c], wl, aL[n]);
                aR[n] = fmaf(hr[n][c], wr, aR[n]);
            }
        }
    }
#pragma unroll
    for (int r = 0; r < NLN; r++) {
        int n = nb + r;
        if (n < N) { g_xl[n * HH + ch] = aL[r]; g_xr[n * HH + ch] = aR[r]; }
    }
}

// one block (128 threads, float2/thread) per destination node: fused GATv2
// scoring + softmax + aggregation + residual + LayerNorm + ReLU.
// No running max (scores O(0.05) -> exp() safe).
__global__ void __launch_bounds__(128)
k_gat(const float* __restrict__ We, const float* __restrict__ att,
      const float* __restrict__ gb, const float* __restrict__ lng,
      const float* __restrict__ lnb, int l) {
    __shared__ float4 ep[ETILE];
    __shared__ float red[4];
    int n = blockIdx.x, t = threadIdx.x;
    int wid = t >> 5, lane = t & 31;
    int ch0 = 2 * t;
    int head = t >> 4;
    int hc = ch0 & 31;
    float2 xr2 = *(const float2*)&g_xr[n * HH + ch0];
    float2 hres = *(const float2*)&g_h[n * HH + ch0];
    float att0 = att[(l * NHEADS + head) * 32 + hc];
    float att1 = att[(l * NHEADS + head) * 32 + hc + 1];
    float we00 = We[(l * 3 + 0) * HH + ch0], we01 = We[(l * 3 + 0) * HH + ch0 + 1];
    float we10 = We[(l * 3 + 1) * HH + ch0], we11 = We[(l * 3 + 1) * HH + ch0 + 1];
    float we20 = We[(l * 3 + 2) * HH + ch0], we21 = We[(l * 3 + 2) * HH + ch0 + 1];
    int e0 = g_roff[n], e1 = g_roff[n + 1];

    float den = 0.f, acc0 = 0.f, acc1 = 0.f;
    for (int t0 = e0; t0 < e1; t0 += ETILE) {
        int cnt = min(ETILE, e1 - t0);
        __syncthreads();
        for (int k = t; k < cnt; k += 128) ep[k] = g_epack[t0 + k];
        __syncthreads();
#pragma unroll 2
        for (int g = 0; g < cnt; g += 4) {
            float2 xv[4];
            float al[4];
#pragma unroll
            for (int u = 0; u < 4; u++) {
                int idx = min(g + u, cnt - 1);
                float4 e = ep[idx];
                int s = __float_as_int(e.x);
                xv[u] = *(const float2*)&g_xl[s * HH + ch0];
                float s0 = xv[u].x + xr2.x + e.y * we00 + e.z * we10 + e.w * we20;
                float s1 = xv[u].y + xr2.y + e.y * we01 + e.z * we11 + e.w * we21;
                s0 = s0 > 0.f ? s0 : 0.2f * s0;
                s1 = s1 > 0.f ? s1 : 0.2f * s1;
                float v = s0 * att0 + s1 * att1;
                al[u] = (g + u < cnt) ? v : -1e30f;
            }
            // multi-reduce: 4 head-sums over 16-lane groups in 5 shfls
            float p0 = (lane & 8) ? al[2] : al[0];
            float q0 = (lane & 8) ? al[0] : al[2];
            float p1 = (lane & 8) ? al[3] : al[1];
            float q1 = (lane & 8) ? al[1] : al[3];
            p0 += __shfl_xor_sync(0xffffffffu, q0, 8);
            p1 += __shfl_xor_sync(0xffffffffu, q1, 8);
            float pa = (lane & 4) ? p1 : p0;
            float qa = (lane & 4) ? p0 : p1;
            pa += __shfl_xor_sync(0xffffffffu, qa, 4);
            pa += __shfl_xor_sync(0xffffffffu, pa, 2);
            pa += __shfl_xor_sync(0xffffffffu, pa, 1);
            int base = lane & 16;
#pragma unroll
            for (int u = 0; u < 4; u++) {
                float w = __expf(__shfl_sync(0xffffffffu, pa, base + (u << 2)));
                den += w;
                acc0 = fmaf(w, xv[u].x, acc0);
                acc1 = fmaf(w, xv[u].y, acc1);
            }
        }
    }
    float inv = 1.0f / den;
    float o0 = acc0 * inv + gb[l * HH + ch0]     + hres.x;
    float o1 = acc1 * inv + gb[l * HH + ch0 + 1] + hres.y;

    // LayerNorm over 256 channels (block reduce over 4 warps), then ReLU
    float v = o0 + o1;
#pragma unroll
    for (int o = 16; o > 0; o >>= 1) v += __shfl_xor_sync(0xffffffffu, v, o);
    if (lane == 0) red[wid] = v;
    __syncthreads();
    float mu = (red[0] + red[1] + red[2] + red[3]) * (1.0f / HH);
    float d0 = o0 - mu, d1 = o1 - mu;
    float q = d0 * d0 + d1 * d1;
#pragma unroll
    for (int o = 16; o > 0; o >>= 1) q += __shfl_xor_sync(0xffffffffu, q, o);
    __syncthreads();
    if (lane == 0) red[wid] = q;
    __syncthreads();
    float var = (red[0] + red[1] + red[2] + red[3]) * (1.0f / HH);
    float rstd = rsqrtf(var + 1e-5f);
    float y0 = d0 * rstd * lng[l * HH + ch0]     + lnb[l * HH + ch0];
    float y1 = d1 * rstd * lng[l * HH + ch0 + 1] + lnb[l * HH + ch0 + 1];
    *(float2*)&g_h[n * HH + ch0] = make_float2(fmaxf(y0, 0.f), fmaxf(y1, 0.f));
}

// graph pooling + value head + Potts energy
__global__ void k_graph(const float* __restrict__ v1W, const float* __restrict__ v1b,
                        const float* __restrict__ v2W, const float* __restrict__ v2b,
                        const float* __restrict__ coup, float* __restrict__ out,
                        int N, long long P) {
    __shared__ float gr[2 * HH];
    __shared__ float psum[2][HH];
    __shared__ float pmax[2][HH];
    __shared__ float sred[512];
    int t = threadIdx.x;
    int half = t >> 8, ch = t & 255;
    int nh = N >> 1;
    {
        float s = 0.f, mx = -1e30f;
        for (int n = half * nh; n < (half + 1) * nh; n++) {
            float v = g_h[n * HH + ch];
            s += v; mx = fmaxf(mx, v);
        }
        psum[half][ch] = s; pmax[half][ch] = mx;
    }
    __syncthreads();
    if (t < HH) {
        gr[t] = (psum[0][t] + psum[1][t]) / (float)N;
        gr[HH + t] = fmaxf(pmax[0][t], pmax[1][t]);
    }
    __syncthreads();
    float contrib = 0.f;
    if (t < HH) {
        float a = v1b[t];
        for (int c = 0; c < 2 * HH; c++) a = fmaf(gr[c], v1W[c * HH + t], a);
        a = fmaxf(a, 0.f);
        contrib = a * v2W[t];
    }
    sred[t] = contrib;
    __syncthreads();
    for (int off = 256; off > 0; off >>= 1) {
        if (t < off) sred[t] += sred[t + off];
        __syncthreads();
    }
    if (t == 0) out[P] = sred[0] + v2b[0];

    float e = 0.f;
    for (int n = t; n < N; n += 512) {
        float d1 = (float)g_deg1[n], d2 = (float)g_deg2[n];
        e += d1 * d1 + d2 * d2;
    }
    __syncthreads();
    sred[t] = e;
    __syncthreads();
    for (int off = 256; off > 0; off >>= 1) {
        if (t < off) sred[t] += sred[t + off];
        __syncthreads();
    }
    if (t == 0) out[P + 1] = coup[0] * sred[0] / (2.0f * (float)N);
}

// A = h @ p1_W[:H] + p1_b,  B = h @ p1_W[H:]   (factorized pair-MLP layer 1)
__global__ void __launch_bounds__(128)
k_AB(const float* __restrict__ p1W, const float* __restrict__ p1b, int N) {
    __shared__ float hr[NLN][HH];
    __shared__ float wbuf[2][2][NLC][128];
    int nb = blockIdx.x * NLN;
    int chb = blockIdx.y * 128;
    int t = threadIdx.x;
    int ch = chb + t;
    for (int idx = t; idx < NLN * HH; idx += 128) {
        int r = idx >> 8, c = idx & 255;
        int n = nb + r;
        hr[r][c] = (n < N) ? g_h[n * HH + c] : 0.f;
    }
    const float* WA = p1W + chb;                   // rows 0..255
    const float* WB = p1W + (size_t)HH * HH + chb; // rows 256..511
#pragma unroll
    for (int r = 0; r < NLC; r++) {
        wbuf[0][0][r][t] = WA[r * HH + t];
        wbuf[0][1][r][t] = WB[r * HH + t];
    }
    float a[NLN], b[NLN];
    float bv = p1b[ch];
#pragma unroll
    for (int r = 0; r < NLN; r++) { a[r] = bv; b[r] = 0.f; }
    const int nch = HH / NLC;
    for (int k = 0; k < nch; k++) {
        int buf = k & 1;
        __syncthreads();
        if (k + 1 < nch) {
            int c0 = (k + 1) * NLC;
#pragma unroll
            for (int r = 0; r < NLC; r++) {
                wbuf[buf ^ 1][0][r][t] = WA[(c0 + r) * HH + t];
                wbuf[buf ^ 1][1][r][t] = WB[(c0 + r) * HH + t];
            }
        }
#pragma unroll
        for (int r = 0; r < NLC; r++) {
            int c = k * NLC + r;
            float wt = wbuf[buf][0][r][t];
            float wb = wbuf[buf][1][r][t];
#pragma unroll
            for (int n = 0; n < NLN; n++) {
                a[n] = fmaf(hr[n][c], wt, a[n]);
                b[n] = fmaf(hr[n][c], wb, b[n]);
            }
        }
    }
#pragma unroll
    for (int r = 0; r < NLN; r++) {
        int n = nb + r;
        if (n < N) { g_A[n * HH + ch] = a[r]; g_B[n * HH + ch] = b[r]; }
    }
}

// fused all-pairs MLP: q = relu(A[i]+B[j]); out2 = relu(q@W2+b2); logit=out2.w3+b3
// 512 threads: ty(0..15)+16r covers 128 pairs, tx(0..31) covers 128 outputs as
// 2 u64. Inner loop batched over 2 c's: a-fragments via LDS.128 (qs2 rows are
// contiguous), b via LDS.64 -> 32 fma2 per 12 LDS issue slots.
#define PCH 16
__global__ void __launch_bounds__(512, 2)
k_pairs(const float* __restrict__ p2W, const float* __restrict__ p2b,
        const float* __restrict__ p3W, const float* __restrict__ p3b,
        float* __restrict__ out, int N, long long P) {
    __shared__ __align__(16) unsigned long long qs2[128][PCH]; // (q,q) dup 16KB
    __shared__ unsigned long long w2s[PCH][64];    // packed weight pairs 8KB
    __shared__ int si[128], sj[128];
    int tid = threadIdx.x;
    int tx = tid & 31, ty = tid >> 5;
    long long pbase = (long long)blockIdx.x * 128;

    if (tid < 128) {
        long long p = pbase + tid;
        if (p > P - 1) p = P - 1;
        float tn = 2.0f * N - 1.0f;
        float disc = fmaxf(tn * tn - 8.0f * (float)p, 0.0f);
        int i = (int)((tn - sqrtf(disc)) * 0.5f);
        if (i < 0) i = 0;
        if (i > N - 2) i = N - 2;
        while ((long long)(i + 1) * (2 * N - 2 - i) / 2 <= p) i++;
        while ((long long)i * (2 * N - 1 - i) / 2 > p) i--;
        int j = i + 1 + (int)(p - (long long)i * (2 * N - 1 - i) / 2);
        si[tid] = i; sj[tid] = j;
    }

    unsigned long long acc[8][2] = {};
    for (int c0 = 0; c0 < HH; c0 += PCH) {
        __syncthreads();
        for (int idx = tid; idx < 128 * PCH; idx += 512) {
            int pr = idx >> 4, c = idx & 15;
            float q = g_A[si[pr] * HH + c0 + c] + g_B[sj[pr] * HH + c0 + c];
            q = q > 0.f ? q : 0.f;
            qs2[pr][c] = pk2(q, q);
        }
        for (int idx = tid; idx < PCH * 64; idx += 512) {
            int c = idx >> 6, id = idx & 63;
            int kq = id >> 5, kt = id & 31;
            w2s[c][id] = pk2(p2W[(c0 + c) * 128 + kt + 64 * kq],
                             p2W[(c0 + c) * 128 + kt + 64 * kq + 32]);
        }
        __syncthreads();
#pragma unroll
        for (int c = 0; c < PCH; c += 2) {
            unsigned long long b00 = w2s[c][tx];
            unsigned long long b01 = w2s[c][tx + 32];
            unsigned long long b10 = w2s[c + 1][tx];
            unsigned long long b11 = w2s[c + 1][tx + 32];
#pragma unroll
            for (int r = 0; r < 8; r++) {
                ulonglong2 a2 = *(const ulonglong2*)&qs2[ty + 16 * r][c];
                fma2(acc[r][0], a2.x, b00);
                fma2(acc[r][1], a2.x, b01);
                fma2(acc[r][0], a2.y, b10);
                fma2(acc[r][1], a2.y, b11);
            }
        }
    }

    // epilogue: k indices: acc[r][0] -> (tx, tx+32); acc[r][1] -> (tx+64, tx+96)
    float bb0 = p2b[tx],      bb1 = p2b[tx + 32];
    float bb2 = p2b[tx + 64], bb3 = p2b[tx + 96];
    float w30 = p3W[tx],      w31 = p3W[tx + 32];
    float w32 = p3W[tx + 64], w33 = p3W[tx + 96];
    float b3v = p3b[0];
#pragma unroll
    for (int r = 0; r < 8; r++) {
        float v0, v1, v2, v3;
        upk2(acc[r][0], v0, v1);
        upk2(acc[r][1], v2, v3);
        float part = 0.f;
        part = fmaf(fmaxf(v0 + bb0, 0.f), w30, part);
        part = fmaf(fmaxf(v1 + bb1, 0.f), w31, part);
        part = fmaf(fmaxf(v2 + bb2, 0.f), w32, part);
        part = fmaf(fmaxf(v3 + bb3, 0.f), w33, part);
#pragma unroll
        for (int o = 16; o > 0; o >>= 1)
            part += __shfl_xor_sync(0xffffffffu, part, o);
        if (tx == 0) {
            long long p = pbase + ty + 16 * r;
            if (p < P) out[p] = part + b3v;
        }
    }
}

// ---------------- launch ------------------------------------------------------
extern "C" void kernel_launch(void* const* d_in, const int* in_sizes, int n_in,
                              void* d_out, int out_size) {
    const float* x    = (const float*)d_in[0];
    const int*   ei   = (const int*)  d_in[1];
    const float* ea   = (const float*)d_in[2];
    const float* embW = (const float*)d_in[3];
    const float* embB = (const float*)d_in[4];
    const float* Wl   = (const float*)d_in[5];
    const float* bl   = (const float*)d_in[6];
    const float* Wr   = (const float*)d_in[7];
    const float* br   = (const float*)d_in[8];
    const float* We   = (const float*)d_in[9];
    const float* att  = (const float*)d_in[10];
    const float* gb   = (const float*)d_in[11];
    const float* lng  = (const float*)d_in[12];
    const float* lnb  = (const float*)d_in[13];
    const float* p1W  = (const float*)d_in[14];
    const float* p1b  = (const float*)d_in[15];
    const float* p2W  = (const float*)d_in[16];
    const float* p2b  = (const float*)d_in[17];
    const float* p3W  = (const float*)d_in[18];
    const float* p3b  = (const float*)d_in[19];
    const float* v1W  = (const float*)d_in[20];
    const float* v1b  = (const float*)d_in[21];
    const float* v2W  = (const float*)d_in[22];
    const float* v2b  = (const float*)d_in[23];
    const float* coup = (const float*)d_in[24];

    int N = in_sizes[0];
    int E = in_sizes[1] / 2;
    long long P = (long long)N * (N - 1) / 2;
    float* out = (float*)d_out;

    dim3 nl((N + NLN - 1) / NLN, 2);
    k_embinit<<<N, 256>>>(x, embW, embB);
    k_edge_stats<<<(E + 255) / 256, 256>>>(ei, ea, E);
    k_nodelin<<<nl, 128>>>(Wl, bl, Wr, br, 0, N);
    k_scan<<<1, 1024>>>(N);
    k_scatter<<<(E + 255) / 256, 256>>>(ei, ea, E);
    k_gat<<<N, 128>>>(We, att, gb, lng, lnb, 0);
    for (int l = 1; l < 4; l++) {
        k_nodelin<<<nl, 128>>>(Wl, bl, Wr, br, l, N);
        k_gat<<<N, 128>>>(We, att, gb, lng, lnb, l);
    }
    k_graph<<<1, 512>>>(v1W, v1b, v2W, v2b, coup, out, N, P);
    k_AB<<<nl, 128>>>(p1W, p1b, N);
    int pblocks = (int)((P + 127) / 128);
    k_pairs<<<pblocks, 512>>>(p2W, p2b, p3W, p3b, out, N, P);
}